// round 9
// baseline (speedup 1.0000x reference)
#include <cuda_runtime.h>
#include <cstdint>

#define B_ 128
#define N_ 2048
#define D_ 128
#define H_ 8
#define CL 8
#define TPB 256

typedef unsigned long long ull;

// smem layout (bytes)
#define OFF_MBAR   0
#define OFF_PART   64        // 128 f : this CTA's partial column sums
#define OFF_CTX    640       // 384 f : full context (mean | first | curr)
#define OFF_QIN    2176      // 16 f  : local qin slice
#define OFF_QINF   2240      // 128 f : full qin
#define OFF_QSL    2752      // 16 f  : local q slice
#define OFF_QF     2816      // 128 f : full q
#define OFF_QKSL   3328      // 128 f : local head qk slice
#define OFF_QKBSL  3840      // 1 f   : local head bias
#define OFF_QK     3904      // 1024 f: full qk (16B aligned)
#define OFF_QKB    8000      // 8 f
#define OFF_HSUM   8032      // 8 f   : local per-head exp-sums
#define OFF_TOT    8064      // 64 f
#define OFF_INV    8320      // 8 f
#define OFF_RED    8384      // 256 float4 = 4096 B (mean reduce scratch)
#define OFF_EXP    12480     // 256*9 f = 9216 B (exp scores, stride 9)
#define OFF_X      21696     // 131072 B (256 rows x 128 f, TMA resident)
#define SMEM_TOTAL (OFF_X + 131072)

__device__ __forceinline__ void fma2(ull& d, ull a, ull b) {
    asm("fma.rn.f32x2 %0, %1, %2, %0;" : "+l"(d) : "l"(a), "l"(b));
}
__device__ __forceinline__ float lo32(ull v) { return __uint_as_float((unsigned)v); }
__device__ __forceinline__ float hi32(ull v) { return __uint_as_float((unsigned)(v >> 32)); }
__device__ __forceinline__ uint32_t smem_u32(const void* p) {
    return (uint32_t)__cvta_generic_to_shared(p);
}
__device__ __forceinline__ void mbar_init1(uint32_t a) {
    asm volatile("mbarrier.init.shared.b64 [%0], 1;" :: "r"(a) : "memory");
}
__device__ __forceinline__ void mbar_expect(uint32_t a, uint32_t bytes) {
    asm volatile("mbarrier.arrive.expect_tx.shared.b64 _, [%0], %1;"
                 :: "r"(a), "r"(bytes) : "memory");
}
__device__ __forceinline__ void bulk_g2s(uint32_t dst, const void* src,
                                         uint32_t bytes, uint32_t mbar) {
    asm volatile(
        "cp.async.bulk.shared::cluster.global.mbarrier::complete_tx::bytes "
        "[%0], [%1], %2, [%3];"
        :: "r"(dst), "l"(src), "r"(bytes), "r"(mbar) : "memory");
}
__device__ __forceinline__ void mbar_wait(uint32_t mbar, uint32_t phase) {
    uint32_t done = 0;
    while (!done) {
        asm volatile(
            "{\n\t.reg .pred p;\n\t"
            "mbarrier.try_wait.parity.acquire.cta.shared::cta.b64 p, [%1], %2, 0x989680;\n\t"
            "selp.b32 %0, 1, 0, p;\n\t}"
            : "=r"(done) : "r"(mbar), "r"(phase) : "memory");
    }
}
__device__ __forceinline__ void fence_async() {
    asm volatile("fence.proxy.async.shared::cta;" ::: "memory");
}
__device__ __forceinline__ void cluster_sync() {
    asm volatile("barrier.cluster.arrive.aligned;" ::: "memory");
    asm volatile("barrier.cluster.wait.aligned;" ::: "memory");
}
// DSMEM scalar read from cluster CTA `rank` at this-CTA-layout address `laddr`
__device__ __forceinline__ float ld_dsmem(uint32_t laddr, uint32_t rank) {
    uint32_t ra; float v;
    asm volatile("mapa.shared::cluster.u32 %0, %1, %2;" : "=r"(ra) : "r"(laddr), "r"(rank));
    asm volatile("ld.volatile.shared::cluster.f32 %0, [%1];" : "=f"(v) : "r"(ra) : "memory");
    return v;
}

extern "C" __global__ void __launch_bounds__(TPB, 1) __cluster_dims__(CL, 1, 1)
actor_fused(const float* __restrict__ x,
            const int* __restrict__ first_node,
            const int* __restrict__ current_node,
            const void* __restrict__ mask_raw,
            const float* __restrict__ W_lin,
            const float* __restrict__ b_lin,
            const float* __restrict__ Wq,
            const float* __restrict__ bq,
            const float* __restrict__ Wk,
            const float* __restrict__ bk,
            float* __restrict__ out)
{
    extern __shared__ char sm[];
    float* smf = (float*)sm;
    const uint32_t smb = smem_u32(sm);
    const int t    = threadIdx.x;
    const int lane = t & 31;
    const int w    = t >> 5;
    uint32_t rank;
    asm("mov.u32 %0, %%cluster_ctarank;" : "=r"(rank));
    const int b = blockIdx.x >> 3;

    // ---- kick TMA: this CTA's 256 rows (128 KB) resident in smem ----
    if (t == 0) { mbar_init1(smb + OFF_MBAR); fence_async(); }
    __syncthreads();
    const char* gsrc = (const char*)(x + (size_t)b * (N_ * D_) + (size_t)rank * (256 * D_));
    if (t == 0) {
        mbar_expect(smb + OFF_MBAR, 131072);
        #pragma unroll
        for (int s = 0; s < 8; ++s)
            bulk_g2s(smb + OFF_X + s * 16384, gsrc + (size_t)s * 16384, 16384, smb + OFF_MBAR);
    }

    // ---- independent early work: mask dtype sniff + first/curr gather ----
    int mask_u8;
    {
        // int32-stored bools hold only 0/1 words; u8-packed bools give words >1 w.h.p.
        const uint32_t* mw = (const uint32_t*)mask_raw;
        int pred = (mw[(size_t)b * 512 + t] > 1u) | (mw[(size_t)b * 512 + t + 256] > 1u);
        mask_u8 = __syncthreads_or(pred);
    }
    if (t < 128) {
        int fn = min(max(first_node[b], 0), N_ - 1);
        int cn = min(max(current_node[b], 0), N_ - 1);
        smf[OFF_CTX / 4 + 128 + t] = x[(size_t)b * (N_ * D_) + (size_t)fn * D_ + t];
        smf[OFF_CTX / 4 + 256 + t] = x[(size_t)b * (N_ * D_) + (size_t)cn * D_ + t];
    }

    // ---- wait x, local partial column sums ----
    mbar_wait(smb + OFF_MBAR, 0);
    {
        const float4* x4 = (const float4*)(sm + OFF_X);
        float4 acc = make_float4(0.f, 0.f, 0.f, 0.f);
        #pragma unroll 8
        for (int k = 0; k < 32; ++k) {
            float4 v = x4[t + 256 * k];
            acc.x += v.x; acc.y += v.y; acc.z += v.z; acc.w += v.w;
        }
        ((float4*)(sm + OFF_RED))[t] = acc;
    }
    __syncthreads();
    if (t < 32) {
        const float4* rd = (const float4*)(sm + OFF_RED);
        float4 s = rd[t];
        #pragma unroll
        for (int m = 1; m < 8; ++m) {
            float4 v = rd[t + 32 * m];
            s.x += v.x; s.y += v.y; s.z += v.z; s.w += v.w;
        }
        smf[OFF_PART / 4 + 4 * t + 0] = s.x;
        smf[OFF_PART / 4 + 4 * t + 1] = s.y;
        smf[OFF_PART / 4 + 4 * t + 2] = s.z;
        smf[OFF_PART / 4 + 4 * t + 3] = s.w;
    }
    cluster_sync();                                   // S1: partials visible

    // ---- assemble full mean ----
    if (t < 128) {
        float m = 0.f;
        #pragma unroll
        for (uint32_t r = 0; r < CL; ++r) m += ld_dsmem(smb + OFF_PART + 4 * t, r);
        smf[OFF_CTX / 4 + t] = m * (1.0f / (float)N_);
    }
    __syncthreads();

    // ---- qin slice: outputs 16*rank .. +16 (8 threads per output) ----
    if (t < 128) {
        const int g = t >> 3, sub = t & 7;
        const int i = 16 * (int)rank + g;
        const float4* wr = (const float4*)(W_lin + (size_t)i * 384) + sub * 12;
        const float4* cx = (const float4*)(smf + OFF_CTX / 4) + sub * 12;
        float a = 0.f;
        #pragma unroll
        for (int j = 0; j < 12; ++j) {
            float4 wv = wr[j], cv = cx[j];
            a += wv.x * cv.x + wv.y * cv.y + wv.z * cv.z + wv.w * cv.w;
        }
        a += __shfl_xor_sync(0xffffffffu, a, 1);
        a += __shfl_xor_sync(0xffffffffu, a, 2);
        a += __shfl_xor_sync(0xffffffffu, a, 4);
        if (sub == 0) smf[OFF_QIN / 4 + g] = a + b_lin[i];
    }
    cluster_sync();                                   // S2: qin slices visible
    if (t < 128) smf[OFF_QINF / 4 + t] = ld_dsmem(smb + OFF_QIN + 4 * (t & 15), t >> 4);
    __syncthreads();

    // ---- q slice ----
    if (t < 128) {
        const int g = t >> 3, sub = t & 7;
        const int i = 16 * (int)rank + g;
        const float4* wr = (const float4*)(Wq + (size_t)i * 128) + sub * 4;
        const float4* cx = (const float4*)(smf + OFF_QINF / 4) + sub * 4;
        float a = 0.f;
        #pragma unroll
        for (int j = 0; j < 4; ++j) {
            float4 wv = wr[j], cv = cx[j];
            a += wv.x * cv.x + wv.y * cv.y + wv.z * cv.z + wv.w * cv.w;
        }
        a += __shfl_xor_sync(0xffffffffu, a, 1);
        a += __shfl_xor_sync(0xffffffffu, a, 2);
        a += __shfl_xor_sync(0xffffffffu, a, 4);
        if (sub == 0) smf[OFF_QSL / 4 + g] = a + bq[i];
    }
    cluster_sync();                                   // S3: q slices visible
    if (t < 128) smf[OFF_QF / 4 + t] = ld_dsmem(smb + OFF_QSL + 4 * (t & 15), t >> 4);
    __syncthreads();

    // ---- qk for head = rank: qk[c] = 0.25 * sum_j q[16r+j] * Wk[16r+j, c] ----
    if (t < 128) {
        float a = 0.f;
        #pragma unroll
        for (int j = 0; j < 16; ++j)
            a += smf[OFF_QF / 4 + 16 * (int)rank + j] * Wk[(size_t)(16 * (int)rank + j) * 128 + t];
        smf[OFF_QKSL / 4 + t] = a * 0.25f;
        if (t == 0) {
            float bb = 0.f;
            #pragma unroll
            for (int j = 0; j < 16; ++j)
                bb += smf[OFF_QF / 4 + 16 * (int)rank + j] * bk[16 * (int)rank + j];
            smf[OFF_QKBSL / 4] = bb * 0.25f;
        }
    }
    cluster_sync();                                   // S4: qk slices visible
    {
        #pragma unroll
        for (int m = 0; m < 4; ++m) {
            const int idx = t + 256 * m;              // 0..1023
            const int h = idx >> 7, c = idx & 127;
            smf[OFF_QK / 4 + idx] = ld_dsmem(smb + OFF_QKSL + 4 * c, h);
        }
        if (t < 8) smf[OFF_QKB / 4 + t] = ld_dsmem(smb + OFF_QKBSL, t);
    }
    __syncthreads();

    // ---- scores + exp over resident x (2 heads per lane) ----
    const int qq = lane & 7;
    const int hp = lane >> 3;
    ull qk0[8], qk1[8];
    {
        const ulonglong2* q0 = (const ulonglong2*)(smf + OFF_QK / 4 + (2 * hp) * 128);
        const ulonglong2* q1 = (const ulonglong2*)(smf + OFF_QK / 4 + (2 * hp + 1) * 128);
        #pragma unroll
        for (int j = 0; j < 4; ++j) {
            ulonglong2 v0 = q0[qq + 8 * j];
            ulonglong2 v1 = q1[qq + 8 * j];
            qk0[2 * j] = v0.x; qk0[2 * j + 1] = v0.y;
            qk1[2 * j] = v1.x; qk1[2 * j + 1] = v1.y;
        }
    }
    const float bias0 = smf[OFF_QKB / 4 + 2 * hp];
    const float bias1 = smf[OFF_QKB / 4 + 2 * hp + 1];
    const unsigned char* mb8  = (const unsigned char*)mask_raw + (size_t)b * N_;
    const int*           mb32 = (const int*)mask_raw + (size_t)b * N_;

    for (int rr = 0; rr < 32; ++rr) {
        const int nl = w * 32 + rr;                   // local row 0..255
        const ulonglong2* xr = (const ulonglong2*)(smf + OFF_X / 4 + nl * D_);
        ull acc0 = 0ull, acc1 = 0ull;
        #pragma unroll
        for (int j = 0; j < 4; ++j) {
            ulonglong2 xv = xr[qq + 8 * j];
            fma2(acc0, xv.x, qk0[2 * j]);
            fma2(acc0, xv.y, qk0[2 * j + 1]);
            fma2(acc1, xv.x, qk1[2 * j]);
            fma2(acc1, xv.y, qk1[2 * j + 1]);
        }
        float s0 = lo32(acc0) + hi32(acc0);
        float s1 = lo32(acc1) + hi32(acc1);
        s0 += __shfl_xor_sync(0xffffffffu, s0, 1);
        s0 += __shfl_xor_sync(0xffffffffu, s0, 2);
        s0 += __shfl_xor_sync(0xffffffffu, s0, 4);
        s1 += __shfl_xor_sync(0xffffffffu, s1, 1);
        s1 += __shfl_xor_sync(0xffffffffu, s1, 2);
        s1 += __shfl_xor_sync(0xffffffffu, s1, 4);
        if (qq == 0) {
            const int n = (int)rank * 256 + nl;
            const bool masked = mask_u8 ? (mb8[n] != 0) : (mb32[n] != 0);
            // scores are tiny (|s|<~0.3): exp without max-subtraction is exact in ratio
            smf[OFF_EXP / 4 + nl * 9 + 2 * hp]     = masked ? 0.f : __expf(s0 + bias0);
            smf[OFF_EXP / 4 + nl * 9 + 2 * hp + 1] = masked ? 0.f : __expf(s1 + bias1);
        }
    }
    __syncthreads();

    // ---- local per-head exp sums (warp w sums head w) ----
    if (w < 8) {
        float sum = 0.f;
        #pragma unroll
        for (int k = 0; k < 8; ++k) sum += smf[OFF_EXP / 4 + (lane + 32 * k) * 9 + w];
        #pragma unroll
        for (int o = 16; o > 0; o >>= 1) sum += __shfl_xor_sync(0xffffffffu, sum, o);
        if (lane == 0) smf[OFF_HSUM / 4 + w] = sum;
    }
    cluster_sync();                                   // S5: head sums visible
    if (t < 64) smf[OFF_TOT / 4 + t] = ld_dsmem(smb + OFF_HSUM + 4 * (t & 7), t >> 3);
    __syncthreads();
    if (t < 8) {
        float tot = 0.f;
        #pragma unroll
        for (int r = 0; r < CL; ++r) tot += smf[OFF_TOT / 4 + r * 8 + t];
        smf[OFF_INV / 4 + t] = 0.125f / tot;
    }
    __syncthreads();

    // ---- output: out[b, rank*256 + t] = sum_h exp[t][h] * inv[h] ----
    {
        float a = 0.f;
        #pragma unroll
        for (int h = 0; h < H_; ++h)
            a += smf[OFF_EXP / 4 + t * 9 + h] * smf[OFF_INV / 4 + h];
        out[(size_t)b * N_ + (int)rank * 256 + t] = a;
    }

    cluster_sync();                                   // S6: keep smem alive for peers
}

extern "C" void kernel_launch(void* const* d_in, const int* in_sizes, int n_in,
                              void* d_out, int out_size)
{
    const float* x      = (const float*)d_in[0];
    const int*   fn     = (const int*)d_in[1];
    const int*   cn     = (const int*)d_in[2];
    const void*  mask   = d_in[3];
    const float* W_lin  = (const float*)d_in[4];
    const float* b_lin  = (const float*)d_in[5];
    const float* Wq     = (const float*)d_in[6];
    const float* bq     = (const float*)d_in[7];
    const float* Wk     = (const float*)d_in[8];
    const float* bk     = (const float*)d_in[9];

    cudaFuncSetAttribute(actor_fused,
                         cudaFuncAttributeMaxDynamicSharedMemorySize, SMEM_TOTAL);

    actor_fused<<<B_ * CL, TPB, SMEM_TOTAL>>>(x, fn, cn, mask, W_lin, b_lin,
                                              Wq, bq, Wk, bk, (float*)d_out);
}

// round 10
// speedup vs baseline: 1.7896x; 1.7896x over previous
#include <cuda_runtime.h>
#include <cstdint>

#define B_ 128
#define N_ 2048
#define D_ 128
#define H_ 8
#define CH 16                  // chunks per batch (128 rows = 64 KB each)
#define QK_STRIDE 1032

typedef unsigned long long ull;

// Device scratch (allocation-free contract: __device__ globals)
__device__ float g_part[B_][CH][D_];           // partial column sums
__device__ float g_qk[B_ * QK_STRIDE];         // per-batch folded qk + bias
__device__ float g_scores[B_ * N_ * H_];       // [b][n][h] exp(masked scores) (8 MB)
__device__ float g_hsum[B_][CH][H_];           // per-chunk per-head exp sums
__device__ int   g_mask_u8;                    // 1 if mask stored as bytes, 0 if int32

__device__ __forceinline__ void fma2(ull& d, ull a, ull b) {
    asm("fma.rn.f32x2 %0, %1, %2, %0;" : "+l"(d) : "l"(a), "l"(b));
}
__device__ __forceinline__ float lo32(ull v) { return __uint_as_float((unsigned)v); }
__device__ __forceinline__ float hi32(ull v) { return __uint_as_float((unsigned)(v >> 32)); }
__device__ __forceinline__ uint32_t smem_u32(const void* p) {
    return (uint32_t)__cvta_generic_to_shared(p);
}
__device__ __forceinline__ void mbar_init1(uint32_t a) {
    asm volatile("mbarrier.init.shared.b64 [%0], 1;" :: "r"(a) : "memory");
}
__device__ __forceinline__ void mbar_expect(uint32_t a, uint32_t bytes) {
    asm volatile("mbarrier.arrive.expect_tx.shared.b64 _, [%0], %1;"
                 :: "r"(a), "r"(bytes) : "memory");
}
__device__ __forceinline__ void bulk_g2s(uint32_t dst, const void* src,
                                         uint32_t bytes, uint32_t mbar) {
    asm volatile(
        "cp.async.bulk.shared::cluster.global.mbarrier::complete_tx::bytes "
        "[%0], [%1], %2, [%3];"
        :: "r"(dst), "l"(src), "r"(bytes), "r"(mbar) : "memory");
}
__device__ __forceinline__ void mbar_wait(uint32_t mbar, uint32_t phase) {
    uint32_t done = 0;
    while (!done) {
        asm volatile(
            "{\n\t.reg .pred p;\n\t"
            "mbarrier.try_wait.parity.acquire.cta.shared::cta.b64 p, [%1], %2, 0x989680;\n\t"
            "selp.b32 %0, 1, 0, p;\n\t}"
            : "=r"(done) : "r"(mbar), "r"(phase) : "memory");
    }
}
__device__ __forceinline__ void fence_async() {
    asm volatile("fence.proxy.async.shared::cta;" ::: "memory");
}

// =============== Kernel A1: partial column sums, single-shot TMA chunk ===============
// grid = B_*CH (2048), block = 256. Chunk = 128 rows (64 KB).
// smem: [0,16) mbar | [16, 4112) reduce scratch | [4608, 70144) x chunk
#define KA1_SMEM (4608 + 65536)
extern "C" __global__ void __launch_bounds__(256)
kA1(const float* __restrict__ x, const void* __restrict__ mask_raw)
{
    extern __shared__ char sm[];
    const uint32_t mbar = smem_u32(sm);
    float4* s_red = (float4*)(sm + 16);
    const uint32_t xoff = 4608;

    const int b  = blockIdx.x >> 4;
    const int c  = blockIdx.x & (CH - 1);
    const int t  = threadIdx.x;

    if (t == 0) { mbar_init1(mbar); fence_async(); }
    __syncthreads();

    const char* gsrc = (const char*)(x + (size_t)b * (N_ * D_) + (size_t)c * (128 * D_));
    if (t == 0) {
        mbar_expect(mbar, 65536);
        #pragma unroll
        for (int s = 0; s < 4; ++s)
            bulk_g2s(smem_u32(sm) + xoff + s * 16384, gsrc + (size_t)s * 16384, 16384, mbar);
    }

    if (blockIdx.x == 0) {       // mask dtype sniff: int32 bools hold only 0/1 words
        const uint32_t* mw = (const uint32_t*)mask_raw;
        int pred = 0;
        #pragma unroll
        for (int i = t; i < 2048; i += 256) pred |= (mw[i] > 1u);
        int rr = __syncthreads_or(pred);
        if (t == 0) g_mask_u8 = rr;
    }

    mbar_wait(mbar, 0);
    {
        const float4* x4 = (const float4*)(sm + xoff);
        float4 acc = make_float4(0.f, 0.f, 0.f, 0.f);
        #pragma unroll
        for (int k = 0; k < 16; ++k) {
            float4 v = x4[t + 256 * k];
            acc.x += v.x; acc.y += v.y; acc.z += v.z; acc.w += v.w;
        }
        s_red[t] = acc;
    }
    __syncthreads();
    if (t < 32) {
        float4 s = s_red[t];
        #pragma unroll
        for (int m = 1; m < 8; ++m) {
            float4 v = s_red[t + 32 * m];
            s.x += v.x; s.y += v.y; s.z += v.z; s.w += v.w;
        }
        ((float4*)g_part[b][c])[t] = s;
    }
}

// =============== Kernel A2: combine + context chain -> qk ===============
extern "C" __global__ void __launch_bounds__(128)
kA2(const float* __restrict__ x,
    const int* __restrict__ first_node,
    const int* __restrict__ current_node,
    const float* __restrict__ W_lin,
    const float* __restrict__ b_lin,
    const float* __restrict__ Wq,
    const float* __restrict__ bq,
    const float* __restrict__ Wk,
    const float* __restrict__ bk)
{
    __shared__ __align__(16) float s_ctx[384];
    __shared__ __align__(16) float s_qin[128];
    __shared__ __align__(16) float s_q[128];

    const int b = blockIdx.x;
    const int t = threadIdx.x;
    const float* xb = x + (size_t)b * (N_ * D_);

    {
        float s = 0.f;
        #pragma unroll
        for (int c = 0; c < CH; ++c) s += g_part[b][c][t];
        s_ctx[t] = s * (1.0f / (float)N_);
    }
    {
        int fn = min(max(first_node[b], 0), N_ - 1);
        int cn = min(max(current_node[b], 0), N_ - 1);
        s_ctx[128 + t] = xb[(size_t)fn * D_ + t];
        s_ctx[256 + t] = xb[(size_t)cn * D_ + t];
    }
    __syncthreads();

    {
        const float4* wr = (const float4*)(W_lin + t * 384);
        const float4* c4 = (const float4*)s_ctx;
        float a0 = 0.f, a1 = 0.f;
        #pragma unroll 8
        for (int j = 0; j < 96; j += 2) {
            float4 wv = wr[j],     cv = c4[j];
            a0 += wv.x * cv.x + wv.y * cv.y + wv.z * cv.z + wv.w * cv.w;
            float4 wv2 = wr[j + 1], cv2 = c4[j + 1];
            a1 += wv2.x * cv2.x + wv2.y * cv2.y + wv2.z * cv2.z + wv2.w * cv2.w;
        }
        s_qin[t] = a0 + a1 + b_lin[t];
    }
    __syncthreads();

    {
        const float4* wr = (const float4*)(Wq + t * 128);
        const float4* c4 = (const float4*)s_qin;
        float a0 = 0.f, a1 = 0.f;
        #pragma unroll 8
        for (int j = 0; j < 32; j += 2) {
            float4 wv = wr[j],     cv = c4[j];
            a0 += wv.x * cv.x + wv.y * cv.y + wv.z * cv.z + wv.w * cv.w;
            float4 wv2 = wr[j + 1], cv2 = c4[j + 1];
            a1 += wv2.x * cv2.x + wv2.y * cv2.y + wv2.z * cv2.z + wv2.w * cv2.w;
        }
        s_q[t] = a0 + a1 + bq[t];
    }
    __syncthreads();

    {
        float* qkb = g_qk + (size_t)b * QK_STRIDE;
        #pragma unroll
        for (int h = 0; h < H_; ++h) {
            float a = 0.f;
            #pragma unroll
            for (int j = 0; j < 16; ++j)
                a += s_q[h * 16 + j] * Wk[(h * 16 + j) * 128 + t];
            qkb[h * 128 + t] = a * 0.25f;
        }
        if (t < 8) {
            float a = 0.f;
            #pragma unroll
            for (int j = 0; j < 16; ++j)
                a += s_q[t * 16 + j] * bk[t * 16 + j];
            qkb[1024 + t] = a * 0.25f;
        }
    }
}

// =============== Kernel B: exp(scores) + per-chunk head sums ===============
// grid = B_*CH (2048) REVERSED batches (L2 reuse), block 256.
// Warp w: rows w*16..w*16+15. Lane: qq=lane&7 (chunk), hp=lane>>3 (head pair).
// smem: [0,4096) qk | [4096,4128) bias | [4160,4168) mbar | [4352,4608) s_wh | [4608,+64K) x
#define KB_SMEM (4608 + 65536)
extern "C" __global__ void __launch_bounds__(256)
kB(const float* __restrict__ x, const void* __restrict__ mask_raw)
{
    extern __shared__ char sm[];
    float* s_qk   = (float*)sm;
    float* s_bias = (float*)(sm + 4096);
    const uint32_t mbar = smem_u32(sm) + 4160;
    float* s_wh   = (float*)(sm + 4352);               // [8 warps][8 heads]
    const uint32_t xoff = 4608;

    const int b    = (B_ - 1) - (blockIdx.x >> 4);      // REVERSED for L2 reuse
    const int c    = blockIdx.x & (CH - 1);
    const int t    = threadIdx.x;
    const int lane = t & 31;
    const int w    = t >> 5;
    const int qq   = lane & 7;
    const int hp   = lane >> 3;

    if (t == 0) { mbar_init1(mbar); fence_async(); }
    __syncthreads();

    const char* gsrc = (const char*)(x + (size_t)b * (N_ * D_) + (size_t)c * (128 * D_));
    if (t == 0) {
        mbar_expect(mbar, 65536);
        #pragma unroll
        for (int s = 0; s < 4; ++s)
            bulk_g2s(smem_u32(sm) + xoff + s * 16384, gsrc + (size_t)s * 16384, 16384, mbar);
    }

    // stage qk + bias while TMA flies
    {
        const float* qkb = g_qk + (size_t)b * QK_STRIDE;
        ((float4*)s_qk)[t] = ((const float4*)qkb)[t];
        if (t < 8) s_bias[t] = qkb[1024 + t];
    }
    __syncthreads();

    ull qk0[8], qk1[8];
    {
        const ulonglong2* q0 = (const ulonglong2*)(s_qk + (2 * hp) * 128);
        const ulonglong2* q1 = (const ulonglong2*)(s_qk + (2 * hp + 1) * 128);
        #pragma unroll
        for (int j = 0; j < 4; ++j) {
            ulonglong2 v0 = q0[qq + 8 * j];
            ulonglong2 v1 = q1[qq + 8 * j];
            qk0[2 * j] = v0.x; qk0[2 * j + 1] = v0.y;
            qk1[2 * j] = v1.x; qk1[2 * j + 1] = v1.y;
        }
    }
    const float bias0 = s_bias[2 * hp];
    const float bias1 = s_bias[2 * hp + 1];
    const int mu8 = g_mask_u8;
    const unsigned char* mb8  = (const unsigned char*)mask_raw + (size_t)b * N_;
    const int*           mb32 = (const int*)mask_raw + (size_t)b * N_;
    float* sc = g_scores + (size_t)b * (N_ * H_);

    mbar_wait(mbar, 0);
    const float* xs = (const float*)(sm + xoff);

    float hsum0 = 0.f, hsum1 = 0.f;                     // valid on qq==0 lanes
    #pragma unroll 2
    for (int i = 0; i < 16; ++i) {
        const int row = w * 16 + i;
        const int n   = c * 128 + row;
        const ulonglong2* xr = (const ulonglong2*)(xs + row * D_);
        ull acc0 = 0ull, acc1 = 0ull;
        #pragma unroll
        for (int j = 0; j < 4; ++j) {
            ulonglong2 xv = xr[qq + 8 * j];
            fma2(acc0, xv.x, qk0[2 * j]);
            fma2(acc0, xv.y, qk0[2 * j + 1]);
            fma2(acc1, xv.x, qk1[2 * j]);
            fma2(acc1, xv.y, qk1[2 * j + 1]);
        }
        float s0 = lo32(acc0) + hi32(acc0);
        float s1 = lo32(acc1) + hi32(acc1);
        s0 += __shfl_xor_sync(0xffffffffu, s0, 1);
        s0 += __shfl_xor_sync(0xffffffffu, s0, 2);
        s0 += __shfl_xor_sync(0xffffffffu, s0, 4);
        s1 += __shfl_xor_sync(0xffffffffu, s1, 1);
        s1 += __shfl_xor_sync(0xffffffffu, s1, 2);
        s1 += __shfl_xor_sync(0xffffffffu, s1, 4);
        if (qq == 0) {
            const bool masked = mu8 ? (mb8[n] != 0) : (mb32[n] != 0);
            // scores are tiny (|s| < ~0.5): exp without max-subtraction is safe (R9-validated)
            float e0 = masked ? 0.f : __expf(s0 + bias0);
            float e1 = masked ? 0.f : __expf(s1 + bias1);
            hsum0 += e0;
            hsum1 += e1;
            float2 o; o.x = e0; o.y = e1;
            *(float2*)(sc + (size_t)n * H_ + 2 * hp) = o;
        }
    }
    if (qq == 0) {
        s_wh[w * 8 + 2 * hp]     = hsum0;
        s_wh[w * 8 + 2 * hp + 1] = hsum1;
    }
    __syncthreads();
    if (t < 8) {
        float tot = 0.f;
        #pragma unroll
        for (int ww = 0; ww < 8; ++ww) tot += s_wh[ww * 8 + t];
        g_hsum[b][c][t] = tot;
    }
}

// =============== Kernel C: rescale stream ===============
// grid = B_ (ascending: kB reversed wrote low-b last -> L2-hot), block 1024.
extern "C" __global__ void __launch_bounds__(1024)
kC(float* __restrict__ out)
{
    __shared__ float s_inv[8];
    const int b = blockIdx.x;
    const int t = threadIdx.x;

    if (t < 8) {
        float tot = 0.f;
        #pragma unroll
        for (int c = 0; c < CH; ++c) tot += g_hsum[b][c][t];
        s_inv[t] = 0.125f / tot;
    }
    __syncthreads();

    float inv[H_];
    #pragma unroll
    for (int h = 0; h < H_; ++h) inv[h] = s_inv[h];

    const float4* sc4 = (const float4*)(g_scores + (size_t)b * (N_ * H_));
    float* ob = out + (size_t)b * N_;
    #pragma unroll
    for (int k = 0; k < 2; ++k) {
        const int n = t + 1024 * k;
        float4 e0 = sc4[2 * n];
        float4 e1 = sc4[2 * n + 1];
        ob[n] = e0.x * inv[0] + e0.y * inv[1] + e0.z * inv[2] + e0.w * inv[3]
              + e1.x * inv[4] + e1.y * inv[5] + e1.z * inv[6] + e1.w * inv[7];
    }
}

extern "C" void kernel_launch(void* const* d_in, const int* in_sizes, int n_in,
                              void* d_out, int out_size)
{
    const float* x      = (const float*)d_in[0];
    const int*   fn     = (const int*)d_in[1];
    const int*   cn     = (const int*)d_in[2];
    const void*  mask   = d_in[3];
    const float* W_lin  = (const float*)d_in[4];
    const float* b_lin  = (const float*)d_in[5];
    const float* Wq     = (const float*)d_in[6];
    const float* bq     = (const float*)d_in[7];
    const float* Wk     = (const float*)d_in[8];
    const float* bk     = (const float*)d_in[9];

    static int configured = 0;
    if (!configured) {
        cudaFuncSetAttribute(kA1, cudaFuncAttributeMaxDynamicSharedMemorySize, KA1_SMEM);
        cudaFuncSetAttribute(kB,  cudaFuncAttributeMaxDynamicSharedMemorySize, KB_SMEM);
        configured = 1;
    }

    kA1<<<B_ * CH, 256, KA1_SMEM>>>(x, mask);
    kA2<<<B_, 128>>>(x, fn, cn, W_lin, b_lin, Wq, bq, Wk, bk);
    kB<<<B_ * CH, 256, KB_SMEM>>>(x, mask);
    kC<<<B_, 1024>>>((float*)d_out);
}